// round 1
// baseline (speedup 1.0000x reference)
#include <cuda_runtime.h>
#include <cuda_fp16.h>
#include <cstdint>

// Problem-fixed dims: B=4, S=2048 -> M=8192, D=2048, R=512.
#define MM 8192
#define DD 2048
#define RR 512

// Scratch (device globals; no allocation allowed in kernel_launch).
__device__ __half g_x16[MM * (size_t)DD];   // x cast to fp16, [M][D]
__device__ __half g_h[MM * (size_t)RR];     // stage-1 output fp16, [M][R]
__device__ __half g_win[(size_t)RR * DD];   // B^T for stage 1: [N=R][K=D]
__device__ __half g_wout[(size_t)DD * RR];  // B^T for stage 2: [N=D][K=R]

// ---------------------------------------------------------------------------
// helpers
// ---------------------------------------------------------------------------
__device__ __forceinline__ uint32_t smem_u32(const void* p) {
    return (uint32_t)__cvta_generic_to_shared(p);
}

__device__ __forceinline__ void cp_async16(uint32_t saddr, const void* gaddr) {
    asm volatile("cp.async.cg.shared.global [%0], [%1], 16;\n"
                 :: "r"(saddr), "l"(gaddr));
}

__device__ __forceinline__ void cp_commit() {
    asm volatile("cp.async.commit_group;\n");
}

__device__ __forceinline__ void ldsm4(uint32_t* r, uint32_t addr) {
    asm volatile("ldmatrix.sync.aligned.m8n8.x4.shared.b16 {%0,%1,%2,%3}, [%4];\n"
                 : "=r"(r[0]), "=r"(r[1]), "=r"(r[2]), "=r"(r[3])
                 : "r"(addr));
}

__device__ __forceinline__ void mma16816(float* c, const uint32_t* a, const uint32_t* b) {
    asm volatile(
        "mma.sync.aligned.m16n8k16.row.col.f32.f16.f16.f32 "
        "{%0,%1,%2,%3}, {%4,%5,%6,%7}, {%8,%9}, {%0,%1,%2,%3};\n"
        : "+f"(c[0]), "+f"(c[1]), "+f"(c[2]), "+f"(c[3])
        : "r"(a[0]), "r"(a[1]), "r"(a[2]), "r"(a[3]), "r"(b[0]), "r"(b[1]));
}

// Swizzled smem layout for a [128 rows][32 halves] tile.
// Two logical rows packed per 128B physical row; 16B chunks XOR-swizzled by
// (physrow & 7) -> ldmatrix (8 rows x 16B) and cp.async stores are conflict-free.
__device__ __forceinline__ int tile_off(int r, int kc) {
    int p  = r >> 1;
    int lc = ((r & 1) << 2) | kc;   // 8 chunks per physical row
    int sc = lc ^ (p & 7);
    return p * 128 + sc * 16;       // byte offset
}

// ---------------------------------------------------------------------------
// preprocessing kernels
// ---------------------------------------------------------------------------
__global__ void convert_x_kernel(const float* __restrict__ x) {
    size_t i = ((size_t)blockIdx.x * blockDim.x + threadIdx.x) * 8;
    float4 a = *(const float4*)(x + i);
    float4 b = *(const float4*)(x + i + 4);
    __half2 h0 = __floats2half2_rn(a.x, a.y);
    __half2 h1 = __floats2half2_rn(a.z, a.w);
    __half2 h2 = __floats2half2_rn(b.x, b.y);
    __half2 h3 = __floats2half2_rn(b.z, b.w);
    uint4 v;
    v.x = *(uint32_t*)&h0; v.y = *(uint32_t*)&h1;
    v.z = *(uint32_t*)&h2; v.w = *(uint32_t*)&h3;
    *(uint4*)(g_x16 + i) = v;
}

__device__ __forceinline__ float second_smallest4(float a0, float a1, float a2, float a3) {
    float lo01 = fminf(a0, a1), hi01 = fmaxf(a0, a1);
    float lo23 = fminf(a2, a3), hi23 = fmaxf(a2, a3);
    return fminf(fmaxf(lo01, lo23), fminf(hi01, hi23));
}

__device__ __forceinline__ float shrink1(float w, float t, float s) {
    float a = fabsf(w) - t;
    a = a > 0.f ? a : 0.f;
    return copysignf(a, w) * s;
}

// weight_in [D][R] fp32, 2:4 groups along R; write g_win[r][d] fp16.
__global__ void prep_win_kernel(const float* __restrict__ w, const float* __restrict__ scale_p) {
    int idx = blockIdx.x * blockDim.x + threadIdx.x;   // D * (R/4) threads
    int d  = idx >> 7;          // / (R/4)=128
    int rg = idx & 127;
    float4 wv = *(const float4*)(w + (size_t)d * RR + rg * 4);
    float s = *scale_p;
    float t = second_smallest4(fabsf(wv.x), fabsf(wv.y), fabsf(wv.z), fabsf(wv.w));
    int r0 = rg * 4;
    g_win[(size_t)(r0 + 0) * DD + d] = __float2half_rn(shrink1(wv.x, t, s));
    g_win[(size_t)(r0 + 1) * DD + d] = __float2half_rn(shrink1(wv.y, t, s));
    g_win[(size_t)(r0 + 2) * DD + d] = __float2half_rn(shrink1(wv.z, t, s));
    g_win[(size_t)(r0 + 3) * DD + d] = __float2half_rn(shrink1(wv.w, t, s));
}

// weight_out [D][R] fp32; st24(weight_out.T): groups of 4 along D for fixed r.
// B^T layout for stage2 is [N=D][K=R] == same storage layout as weight_out.
__global__ void prep_wout_kernel(const float* __restrict__ w, const float* __restrict__ scale_p) {
    int idx = blockIdx.x * blockDim.x + threadIdx.x;   // (D/4) * R threads
    int dg = idx >> 9;          // / R=512
    int r  = idx & 511;
    int d0 = dg * 4;
    float w0 = w[(size_t)(d0 + 0) * RR + r];
    float w1 = w[(size_t)(d0 + 1) * RR + r];
    float w2 = w[(size_t)(d0 + 2) * RR + r];
    float w3 = w[(size_t)(d0 + 3) * RR + r];
    float s = *scale_p;
    float t = second_smallest4(fabsf(w0), fabsf(w1), fabsf(w2), fabsf(w3));
    g_wout[(size_t)(d0 + 0) * RR + r] = __float2half_rn(shrink1(w0, t, s));
    g_wout[(size_t)(d0 + 1) * RR + r] = __float2half_rn(shrink1(w1, t, s));
    g_wout[(size_t)(d0 + 2) * RR + r] = __float2half_rn(shrink1(w2, t, s));
    g_wout[(size_t)(d0 + 3) * RR + r] = __float2half_rn(shrink1(w3, t, s));
}

// ---------------------------------------------------------------------------
// Tensor-core GEMM: C[M][N] = A[M][K] * B^T[N][K], fp16 in, fp32 acc.
// BM=128, BN=128, BK=32, 256 threads, warps 4(M)x2(N) -> 32x64 each.
// ---------------------------------------------------------------------------
template<typename OutT, bool HAS_BIAS>
__global__ __launch_bounds__(256, 2) void gemm_tc(
    const __half* __restrict__ A, const __half* __restrict__ Bt,
    OutT* __restrict__ C, const float* __restrict__ bias, int K, int N)
{
    __shared__ __align__(128) uint8_t sAraw[2][8192];
    __shared__ __align__(128) uint8_t sBraw[2][8192];

    const int tid = threadIdx.x;
    const int wid = tid >> 5, ln = tid & 31;
    const int bm = blockIdx.y * 128, bn = blockIdx.x * 128;
    const int warpM = (wid >> 1) * 32;
    const int warpN = (wid & 1) * 64;

    float acc[2][8][4];
#pragma unroll
    for (int i = 0; i < 2; i++)
#pragma unroll
        for (int j = 0; j < 8; j++)
#pragma unroll
            for (int k = 0; k < 4; k++) acc[i][j][k] = 0.f;

    // per-thread cp.async chunk assignment (two chunks of each tile)
    const int ch0 = tid, ch1 = tid + 256;
    const int lr0 = ch0 >> 2, lkc0 = ch0 & 3;
    const int lr1 = ch1 >> 2, lkc1 = ch1 & 3;
    const int offS0 = tile_off(lr0, lkc0);
    const int offS1 = tile_off(lr1, lkc1);

    const uint32_t sAb[2] = { smem_u32(sAraw[0]), smem_u32(sAraw[1]) };
    const uint32_t sBb[2] = { smem_u32(sBraw[0]), smem_u32(sBraw[1]) };

    // per-thread ldmatrix fragment offsets (buf-independent)
    const int mat = ln >> 3;       // 0..3
    const int mr  = ln & 7;
    int offAf[2][2], offBf[4][2];
#pragma unroll
    for (int mt = 0; mt < 2; mt++) {
        int row = warpM + mt * 16 + ((mat & 1) << 3) + mr;
#pragma unroll
        for (int ks = 0; ks < 2; ks++)
            offAf[mt][ks] = tile_off(row, 2 * ks + (mat >> 1));
    }
#pragma unroll
    for (int np = 0; np < 4; np++) {
        int row = warpN + np * 16 + ((mat >> 1) << 3) + mr;
#pragma unroll
        for (int ks = 0; ks < 2; ks++)
            offBf[np][ks] = tile_off(row, 2 * ks + (mat & 1));
    }

    const int KT = K >> 5;

#define LOAD_TILE(kt, buf) do {                                               \
        const __half* Ag = A  + (size_t)bm * K + (size_t)(kt) * 32;           \
        const __half* Bg = Bt + (size_t)bn * K + (size_t)(kt) * 32;           \
        cp_async16(sAb[buf] + offS0, Ag + (size_t)lr0 * K + lkc0 * 8);        \
        cp_async16(sAb[buf] + offS1, Ag + (size_t)lr1 * K + lkc1 * 8);        \
        cp_async16(sBb[buf] + offS0, Bg + (size_t)lr0 * K + lkc0 * 8);        \
        cp_async16(sBb[buf] + offS1, Bg + (size_t)lr1 * K + lkc1 * 8);        \
        cp_commit();                                                          \
    } while (0)

    LOAD_TILE(0, 0);

    for (int kt = 0; kt < KT; kt++) {
        const int buf = kt & 1;
        if (kt + 1 < KT) {
            LOAD_TILE(kt + 1, buf ^ 1);
            asm volatile("cp.async.wait_group 1;\n");
        } else {
            asm volatile("cp.async.wait_group 0;\n");
        }
        __syncthreads();

        const uint32_t aB = sAb[buf], bB = sBb[buf];
#pragma unroll
        for (int ks = 0; ks < 2; ks++) {
            uint32_t af[2][4];
            ldsm4(af[0], aB + offAf[0][ks]);
            ldsm4(af[1], aB + offAf[1][ks]);
            uint32_t bf[8][2];
#pragma unroll
            for (int np = 0; np < 4; np++) {
                uint32_t t[4];
                ldsm4(t, bB + offBf[np][ks]);
                bf[2 * np][0] = t[0]; bf[2 * np][1] = t[1];
                bf[2 * np + 1][0] = t[2]; bf[2 * np + 1][1] = t[3];
            }
#pragma unroll
            for (int mt = 0; mt < 2; mt++)
#pragma unroll
                for (int nt = 0; nt < 8; nt++)
                    mma16816(acc[mt][nt], af[mt], bf[nt]);
        }
        __syncthreads();
    }
#undef LOAD_TILE

    // epilogue
#pragma unroll
    for (int mt = 0; mt < 2; mt++) {
#pragma unroll
        for (int nt = 0; nt < 8; nt++) {
            int m0 = bm + warpM + mt * 16 + (ln >> 2);
            int n0 = bn + warpN + nt * 8 + (ln & 3) * 2;
            float* a = acc[mt][nt];
            if constexpr (HAS_BIAS) {
                float b0 = bias[n0], b1 = bias[n0 + 1];
                float2 v0 = make_float2(a[0] + b0, a[1] + b1);
                float2 v1 = make_float2(a[2] + b0, a[3] + b1);
                *(float2*)((float*)C + (size_t)m0 * N + n0)       = v0;
                *(float2*)((float*)C + (size_t)(m0 + 8) * N + n0) = v1;
            } else {
                __half2 v0 = __floats2half2_rn(a[0], a[1]);
                __half2 v1 = __floats2half2_rn(a[2], a[3]);
                *(__half2*)((__half*)C + (size_t)m0 * N + n0)       = v0;
                *(__half2*)((__half*)C + (size_t)(m0 + 8) * N + n0) = v1;
            }
        }
    }
}

// ---------------------------------------------------------------------------
extern "C" void kernel_launch(void* const* d_in, const int* in_sizes, int n_in,
                              void* d_out, int out_size)
{
    const float* x    = (const float*)d_in[0];
    const float* w_in = (const float*)d_in[1];
    const float* w_out= (const float*)d_in[2];
    const float* bias = (const float*)d_in[3];
    const float* s_in = (const float*)d_in[4];
    const float* s_out= (const float*)d_in[5];
    float* out = (float*)d_out;

    __half *x16, *h, *win, *wout;
    cudaGetSymbolAddress((void**)&x16,  g_x16);
    cudaGetSymbolAddress((void**)&h,    g_h);
    cudaGetSymbolAddress((void**)&win,  g_win);
    cudaGetSymbolAddress((void**)&wout, g_wout);

    // 1) x fp32 -> fp16  (16.7M elems, 8 per thread)
    convert_x_kernel<<<(MM * (size_t)DD) / (256 * 8), 256>>>(x);
    // 2) soft-threshold weights into B^T fp16 layouts
    prep_win_kernel<<<(DD * (RR / 4)) / 256, 256>>>(w_in, s_in);
    prep_wout_kernel<<<((DD / 4) * RR) / 256, 256>>>(w_out, s_out);

    // 3) stage 1: h[M][R] = x16[M][D] @ win^T   (N=512 -> 4 col tiles)
    {
        dim3 grid(RR / 128, MM / 128);
        gemm_tc<__half, false><<<grid, 256>>>(x16, win, h, nullptr, DD, RR);
    }
    // 4) stage 2: out[M][D] = h[M][R] @ wout^T + bias
    {
        dim3 grid(DD / 128, MM / 128);
        gemm_tc<float, true><<<grid, 256>>>(h, wout, out, bias, RR, DD);
    }
}

// round 3
// speedup vs baseline: 1.0083x; 1.0083x over previous
#include <cuda_runtime.h>
#include <cuda_fp16.h>
#include <cstdint>

// Problem-fixed dims: B=4, S=2048 -> M=8192, D=2048, R=512.
#define MM 8192
#define DD 2048
#define RR 512

// Scratch (device globals; no allocation allowed in kernel_launch).
__device__ __half g_x16[MM * (size_t)DD];   // x cast to fp16, [M][D]
__device__ __half g_h[MM * (size_t)RR];     // stage-1 output fp16, [M][R]
__device__ __half g_win[(size_t)RR * DD];   // B^T for stage 1: [N=R][K=D]
__device__ __half g_wout[(size_t)DD * RR];  // B^T for stage 2: [N=D][K=R]

// ---------------------------------------------------------------------------
// helpers
// ---------------------------------------------------------------------------
__device__ __forceinline__ uint32_t smem_u32(const void* p) {
    return (uint32_t)__cvta_generic_to_shared(p);
}
__device__ __forceinline__ void cp_async16(uint32_t saddr, const void* gaddr) {
    asm volatile("cp.async.cg.shared.global [%0], [%1], 16;\n"
                 :: "r"(saddr), "l"(gaddr));
}
__device__ __forceinline__ void cp_commit() {
    asm volatile("cp.async.commit_group;\n");
}
template<int N>
__device__ __forceinline__ void cp_wait() {
    asm volatile("cp.async.wait_group %0;\n" :: "n"(N));
}
__device__ __forceinline__ void ldsm4(uint32_t* r, uint32_t addr) {
    asm volatile("ldmatrix.sync.aligned.m8n8.x4.shared.b16 {%0,%1,%2,%3}, [%4];\n"
                 : "=r"(r[0]), "=r"(r[1]), "=r"(r[2]), "=r"(r[3])
                 : "r"(addr));
}
__device__ __forceinline__ void mma16816(float* c, const uint32_t* a, const uint32_t* b) {
    asm volatile(
        "mma.sync.aligned.m16n8k16.row.col.f32.f16.f16.f32 "
        "{%0,%1,%2,%3}, {%4,%5,%6,%7}, {%8,%9}, {%0,%1,%2,%3};\n"
        : "+f"(c[0]), "+f"(c[1]), "+f"(c[2]), "+f"(c[3])
        : "r"(a[0]), "r"(a[1]), "r"(a[2]), "r"(a[3]), "r"(b[0]), "r"(b[1]));
}

// ---------------------------------------------------------------------------
// preprocessing kernels
// ---------------------------------------------------------------------------
__global__ void convert_x_kernel(const float* __restrict__ x) {
    size_t i = ((size_t)blockIdx.x * blockDim.x + threadIdx.x) * 8;
    float4 a = *(const float4*)(x + i);
    float4 b = *(const float4*)(x + i + 4);
    __half2 h0 = __floats2half2_rn(a.x, a.y);
    __half2 h1 = __floats2half2_rn(a.z, a.w);
    __half2 h2 = __floats2half2_rn(b.x, b.y);
    __half2 h3 = __floats2half2_rn(b.z, b.w);
    uint4 v;
    v.x = *(uint32_t*)&h0; v.y = *(uint32_t*)&h1;
    v.z = *(uint32_t*)&h2; v.w = *(uint32_t*)&h3;
    *(uint4*)(g_x16 + i) = v;
}

__device__ __forceinline__ float second_smallest4(float a0, float a1, float a2, float a3) {
    float lo01 = fminf(a0, a1), hi01 = fmaxf(a0, a1);
    float lo23 = fminf(a2, a3), hi23 = fmaxf(a2, a3);
    return fminf(fmaxf(lo01, lo23), fminf(hi01, hi23));
}
__device__ __forceinline__ float shrink1(float w, float t, float s) {
    float a = fabsf(w) - t;
    a = a > 0.f ? a : 0.f;
    return copysignf(a, w) * s;
}

__global__ void prep_win_kernel(const float* __restrict__ w, const float* __restrict__ scale_p) {
    int idx = blockIdx.x * blockDim.x + threadIdx.x;
    int d  = idx >> 7;
    int rg = idx & 127;
    float4 wv = *(const float4*)(w + (size_t)d * RR + rg * 4);
    float s = *scale_p;
    float t = second_smallest4(fabsf(wv.x), fabsf(wv.y), fabsf(wv.z), fabsf(wv.w));
    int r0 = rg * 4;
    g_win[(size_t)(r0 + 0) * DD + d] = __float2half_rn(shrink1(wv.x, t, s));
    g_win[(size_t)(r0 + 1) * DD + d] = __float2half_rn(shrink1(wv.y, t, s));
    g_win[(size_t)(r0 + 2) * DD + d] = __float2half_rn(shrink1(wv.z, t, s));
    g_win[(size_t)(r0 + 3) * DD + d] = __float2half_rn(shrink1(wv.w, t, s));
}

__global__ void prep_wout_kernel(const float* __restrict__ w, const float* __restrict__ scale_p) {
    int idx = blockIdx.x * blockDim.x + threadIdx.x;
    int dg = idx >> 9;
    int r  = idx & 511;
    int d0 = dg * 4;
    float w0 = w[(size_t)(d0 + 0) * RR + r];
    float w1 = w[(size_t)(d0 + 1) * RR + r];
    float w2 = w[(size_t)(d0 + 2) * RR + r];
    float w3 = w[(size_t)(d0 + 3) * RR + r];
    float s = *scale_p;
    float t = second_smallest4(fabsf(w0), fabsf(w1), fabsf(w2), fabsf(w3));
    g_wout[(size_t)(d0 + 0) * RR + r] = __float2half_rn(shrink1(w0, t, s));
    g_wout[(size_t)(d0 + 1) * RR + r] = __float2half_rn(shrink1(w1, t, s));
    g_wout[(size_t)(d0 + 2) * RR + r] = __float2half_rn(shrink1(w2, t, s));
    g_wout[(size_t)(d0 + 3) * RR + r] = __float2half_rn(shrink1(w3, t, s));
}

// ---------------------------------------------------------------------------
// HMMA GEMM: C[M][N] = A[M][K] * Bt[N][K], fp16 in, fp32 acc.
// BM=128, BN=128, BK=64, DEPTH=3 cp.async ring, 256 threads, warps 4(M)x2(N).
// One __syncthreads per K-iter; loads for kt+2 issued before compute of kt.
// Smem tile: row r (128B) with 16B-chunk swizzle c^(r&7): conflict-free for
// both cp.async stores and ldmatrix reads.
// ---------------------------------------------------------------------------
template<typename OutT, bool HAS_BIAS>
__global__ __launch_bounds__(256, 2) void gemm_tc(
    const __half* __restrict__ A, const __half* __restrict__ Bt,
    OutT* __restrict__ C, const float* __restrict__ bias, int K, int N)
{
    constexpr int ABYTES = 128 * 128;      // 128 rows x 64 halves
    constexpr int STAGE  = 2 * ABYTES;     // A + B
    constexpr int DEPTH  = 3;

    extern __shared__ __align__(1024) uint8_t dsmem[];
    const uint32_t sbase = (smem_u32(dsmem) + 1023u) & ~1023u;

    const int tid = threadIdx.x;
    const int wid = tid >> 5, ln = tid & 31;
    const int bm = blockIdx.y * 128, bn = blockIdx.x * 128;
    const int warpM = (wid >> 1) * 32;
    const int warpN = (wid & 1) * 64;

    float acc[2][8][4];
#pragma unroll
    for (int i = 0; i < 2; i++)
#pragma unroll
        for (int j = 0; j < 8; j++)
#pragma unroll
            for (int k = 0; k < 4; k++) acc[i][j][k] = 0.f;

    // ldmatrix fragment row addressing (chunk computed per ks)
    const int mat = ln >> 3;       // 0..3
    const int mr  = ln & 7;
    const int aHi = mat >> 1;      // A chunk offset within ks pair
    const int bHi = mat & 1;       // B chunk offset within ks pair
    uint32_t aRowOff[2]; int aRx[2];
#pragma unroll
    for (int mt = 0; mt < 2; mt++) {
        int row = warpM + mt * 16 + ((mat & 1) << 3) + mr;
        aRowOff[mt] = (uint32_t)(row * 128);
        aRx[mt] = row & 7;
    }
    uint32_t bRowOff[4]; int bRx[4];
#pragma unroll
    for (int np = 0; np < 4; np++) {
        int row = warpN + np * 16 + ((mat >> 1) << 3) + mr;
        bRowOff[np] = (uint32_t)(row * 128);
        bRx[np] = row & 7;
    }

    const int KT = K >> 6;

    auto load_stage = [&](int kt, int s) {
        const uint32_t aS = sbase + (uint32_t)s * STAGE;
        const uint32_t bS = aS + ABYTES;
        const __half* Ag = A  + (size_t)bm * K + (size_t)kt * 64;
        const __half* Bg = Bt + (size_t)bn * K + (size_t)kt * 64;
#pragma unroll
        for (int i = 0; i < 4; i++) {
            int l = tid + i * 256;
            int row = l >> 3, kc = l & 7;
            uint32_t soff = (uint32_t)(row * 128 + ((kc ^ (row & 7)) * 16));
            cp_async16(aS + soff, Ag + (size_t)row * K + kc * 8);
            cp_async16(bS + soff, Bg + (size_t)row * K + kc * 8);
        }
        cp_commit();
    };

    load_stage(0, 0);
    load_stage(1, 1);

    for (int kt = 0; kt < KT; kt++) {
        cp_wait<1>();
        __syncthreads();
        if (kt + 2 < KT) load_stage(kt + 2, (kt + 2) % DEPTH);
        else cp_commit();                      // keep group counting uniform

        const uint32_t aB = sbase + (uint32_t)(kt % DEPTH) * STAGE;
        const uint32_t bB = aB + ABYTES;
#pragma unroll
        for (int ks = 0; ks < 4; ks++) {
            uint32_t af[2][4];
#pragma unroll
            for (int mt = 0; mt < 2; mt++)
                ldsm4(af[mt], aB + aRowOff[mt] + (uint32_t)((((2 * ks + aHi) ^ aRx[mt])) * 16));
            uint32_t bf[8][2];
#pragma unroll
            for (int np = 0; np < 4; np++) {
                uint32_t t[4];
                ldsm4(t, bB + bRowOff[np] + (uint32_t)((((2 * ks + bHi) ^ bRx[np])) * 16));
                bf[2 * np][0] = t[0]; bf[2 * np][1] = t[1];
                bf[2 * np + 1][0] = t[2]; bf[2 * np + 1][1] = t[3];
            }
#pragma unroll
            for (int mt = 0; mt < 2; mt++)
#pragma unroll
                for (int nt = 0; nt < 8; nt++)
                    mma16816(acc[mt][nt], af[mt], bf[nt]);
        }
    }

    // epilogue
#pragma unroll
    for (int mt = 0; mt < 2; mt++) {
#pragma unroll
        for (int nt = 0; nt < 8; nt++) {
            int m0 = bm + warpM + mt * 16 + (ln >> 2);
            int n0 = bn + warpN + nt * 8 + (ln & 3) * 2;
            float* a = acc[mt][nt];
            if constexpr (HAS_BIAS) {
                float b0 = bias[n0], b1 = bias[n0 + 1];
                float2 v0 = make_float2(a[0] + b0, a[1] + b1);
                float2 v1 = make_float2(a[2] + b0, a[3] + b1);
                *(float2*)((float*)C + (size_t)m0 * N + n0)       = v0;
                *(float2*)((float*)C + (size_t)(m0 + 8) * N + n0) = v1;
            } else {
                __half2 v0 = __floats2half2_rn(a[0], a[1]);
                __half2 v1 = __floats2half2_rn(a[2], a[3]);
                *(__half2*)((__half*)C + (size_t)m0 * N + n0)       = v0;
                *(__half2*)((__half*)C + (size_t)(m0 + 8) * N + n0) = v1;
            }
        }
    }
}

// ---------------------------------------------------------------------------
extern "C" void kernel_launch(void* const* d_in, const int* in_sizes, int n_in,
                              void* d_out, int out_size)
{
    const float* x    = (const float*)d_in[0];
    const float* w_in = (const float*)d_in[1];
    const float* w_out= (const float*)d_in[2];
    const float* bias = (const float*)d_in[3];
    const float* s_in = (const float*)d_in[4];
    const float* s_out= (const float*)d_in[5];
    float* out = (float*)d_out;

    __half *x16, *h, *win, *wout;
    cudaGetSymbolAddress((void**)&x16,  g_x16);
    cudaGetSymbolAddress((void**)&h,    g_h);
    cudaGetSymbolAddress((void**)&win,  g_win);
    cudaGetSymbolAddress((void**)&wout, g_wout);

    constexpr int SMEM = 3 * (2 * 128 * 128) + 1024;   // 3 stages + align pad

    static bool attr_set = false;
    cudaFuncSetAttribute(gemm_tc<__half, false>,
                         cudaFuncAttributeMaxDynamicSharedMemorySize, SMEM);
    cudaFuncSetAttribute(gemm_tc<float, true>,
                         cudaFuncAttributeMaxDynamicSharedMemorySize, SMEM);
    (void)attr_set;

    // 1) x fp32 -> fp16
    convert_x_kernel<<<(MM * (size_t)DD) / (256 * 8), 256>>>(x);
    // 2) soft-threshold weights into B^T fp16 layouts
    prep_win_kernel<<<(DD * (RR / 4)) / 256, 256>>>(w_in, s_in);
    prep_wout_kernel<<<((DD / 4) * RR) / 256, 256>>>(w_out, s_out);

    // 3) stage 1: h[M][R] = x16 @ win^T   grid (4, 64) = 256 CTAs (1 wave)
    {
        dim3 grid(RR / 128, MM / 128);
        gemm_tc<__half, false><<<grid, 256, SMEM>>>(x16, win, h, nullptr, DD, RR);
    }
    // 4) stage 2: out[M][D] = h @ wout^T + bias   grid (16, 64) = 1024 CTAs
    {
        dim3 grid(DD / 128, MM / 128);
        gemm_tc<float, true><<<grid, 256, SMEM>>>(h, wout, out, bias, RR, DD);
    }
}

// round 4
// speedup vs baseline: 1.0824x; 1.0735x over previous
#include <cuda_runtime.h>
#include <cuda_fp16.h>
#include <cstdint>

// Problem-fixed dims: B=4, S=2048 -> M=8192, D=2048, R=512.
#define MM 8192
#define DD 2048
#define RR 512

// Scratch (device globals; no allocation allowed in kernel_launch).
__device__ __half g_x16[MM * (size_t)DD];   // x cast to fp16, [M][D]
__device__ __half g_h[MM * (size_t)RR];     // stage-1 output fp16, [M][R]
__device__ __half g_win[(size_t)RR * DD];   // B^T for stage 1: [N=R][K=D]
__device__ __half g_wout[(size_t)DD * RR];  // B^T for stage 2: [N=D][K=R]

// ---------------------------------------------------------------------------
// helpers
// ---------------------------------------------------------------------------
__device__ __forceinline__ uint32_t smem_u32(const void* p) {
    return (uint32_t)__cvta_generic_to_shared(p);
}
__device__ __forceinline__ void cp_async16(uint32_t saddr, const void* gaddr) {
    asm volatile("cp.async.cg.shared.global [%0], [%1], 16;\n"
                 :: "r"(saddr), "l"(gaddr));
}
__device__ __forceinline__ void cp_commit() {
    asm volatile("cp.async.commit_group;\n");
}
template<int N>
__device__ __forceinline__ void cp_wait() {
    asm volatile("cp.async.wait_group %0;\n" :: "n"(N));
}
__device__ __forceinline__ void ldsm4(uint32_t* r, uint32_t addr) {
    asm volatile("ldmatrix.sync.aligned.m8n8.x4.shared.b16 {%0,%1,%2,%3}, [%4];\n"
                 : "=r"(r[0]), "=r"(r[1]), "=r"(r[2]), "=r"(r[3])
                 : "r"(addr));
}
__device__ __forceinline__ void mma16816(float* c, const uint32_t* a, const uint32_t* b) {
    asm volatile(
        "mma.sync.aligned.m16n8k16.row.col.f32.f16.f16.f32 "
        "{%0,%1,%2,%3}, {%4,%5,%6,%7}, {%8,%9}, {%0,%1,%2,%3};\n"
        : "+f"(c[0]), "+f"(c[1]), "+f"(c[2]), "+f"(c[3])
        : "r"(a[0]), "r"(a[1]), "r"(a[2]), "r"(a[3]), "r"(b[0]), "r"(b[1]));
}

// ---------------------------------------------------------------------------
// preprocessing kernels
// ---------------------------------------------------------------------------
__global__ void convert_x_kernel(const float* __restrict__ x) {
    size_t i = ((size_t)blockIdx.x * blockDim.x + threadIdx.x) * 8;
    float4 a = *(const float4*)(x + i);
    float4 b = *(const float4*)(x + i + 4);
    __half2 h0 = __floats2half2_rn(a.x, a.y);
    __half2 h1 = __floats2half2_rn(a.z, a.w);
    __half2 h2 = __floats2half2_rn(b.x, b.y);
    __half2 h3 = __floats2half2_rn(b.z, b.w);
    uint4 v;
    v.x = *(uint32_t*)&h0; v.y = *(uint32_t*)&h1;
    v.z = *(uint32_t*)&h2; v.w = *(uint32_t*)&h3;
    *(uint4*)(g_x16 + i) = v;
}

__device__ __forceinline__ float second_smallest4(float a0, float a1, float a2, float a3) {
    float lo01 = fminf(a0, a1), hi01 = fmaxf(a0, a1);
    float lo23 = fminf(a2, a3), hi23 = fmaxf(a2, a3);
    return fminf(fmaxf(lo01, lo23), fminf(hi01, hi23));
}
__device__ __forceinline__ float shrink1(float w, float t, float s) {
    float a = fabsf(w) - t;
    a = a > 0.f ? a : 0.f;
    return copysignf(a, w) * s;
}

__global__ void prep_win_kernel(const float* __restrict__ w, const float* __restrict__ scale_p) {
    int idx = blockIdx.x * blockDim.x + threadIdx.x;
    int d  = idx >> 7;
    int rg = idx & 127;
    float4 wv = *(const float4*)(w + (size_t)d * RR + rg * 4);
    float s = *scale_p;
    float t = second_smallest4(fabsf(wv.x), fabsf(wv.y), fabsf(wv.z), fabsf(wv.w));
    int r0 = rg * 4;
    g_win[(size_t)(r0 + 0) * DD + d] = __float2half_rn(shrink1(wv.x, t, s));
    g_win[(size_t)(r0 + 1) * DD + d] = __float2half_rn(shrink1(wv.y, t, s));
    g_win[(size_t)(r0 + 2) * DD + d] = __float2half_rn(shrink1(wv.z, t, s));
    g_win[(size_t)(r0 + 3) * DD + d] = __float2half_rn(shrink1(wv.w, t, s));
}

__global__ void prep_wout_kernel(const float* __restrict__ w, const float* __restrict__ scale_p) {
    int idx = blockIdx.x * blockDim.x + threadIdx.x;
    int dg = idx >> 9;
    int r  = idx & 511;
    int d0 = dg * 4;
    float w0 = w[(size_t)(d0 + 0) * RR + r];
    float w1 = w[(size_t)(d0 + 1) * RR + r];
    float w2 = w[(size_t)(d0 + 2) * RR + r];
    float w3 = w[(size_t)(d0 + 3) * RR + r];
    float s = *scale_p;
    float t = second_smallest4(fabsf(w0), fabsf(w1), fabsf(w2), fabsf(w3));
    g_wout[(size_t)(d0 + 0) * RR + r] = __float2half_rn(shrink1(w0, t, s));
    g_wout[(size_t)(d0 + 1) * RR + r] = __float2half_rn(shrink1(w1, t, s));
    g_wout[(size_t)(d0 + 2) * RR + r] = __float2half_rn(shrink1(w2, t, s));
    g_wout[(size_t)(d0 + 3) * RR + r] = __float2half_rn(shrink1(w3, t, s));
}

// ---------------------------------------------------------------------------
// HMMA GEMM: C[M][N] = A[M][K] * Bt[N][K], fp16 in, fp32 acc.
// BM=128, BN=128, BK=64. 128 threads, 4 warps in 2x2, warp tile 64x64.
// DEPTH=3 cp.async ring, one __syncthreads per K-iter.
// Smem tile: row r = 128B; 16B chunk swizzle c^(r&7) -> conflict-free
// for cp.async stores and ldmatrix reads.
// ---------------------------------------------------------------------------
template<typename OutT, bool HAS_BIAS>
__global__ __launch_bounds__(128, 2) void gemm_tc(
    const __half* __restrict__ A, const __half* __restrict__ Bt,
    OutT* __restrict__ C, const float* __restrict__ bias, int K, int N)
{
    constexpr int ABYTES = 128 * 128;      // 128 rows x 64 halves
    constexpr int STAGE  = 2 * ABYTES;     // A + B
    constexpr int DEPTH  = 3;

    extern __shared__ __align__(1024) uint8_t dsmem[];
    const uint32_t sbase = (smem_u32(dsmem) + 1023u) & ~1023u;

    const int tid = threadIdx.x;
    const int wid = tid >> 5, ln = tid & 31;
    const int bm = blockIdx.y * 128, bn = blockIdx.x * 128;
    const int warpM = (wid >> 1) * 64;
    const int warpN = (wid & 1) * 64;

    float acc[4][8][4];
#pragma unroll
    for (int i = 0; i < 4; i++)
#pragma unroll
        for (int j = 0; j < 8; j++)
#pragma unroll
            for (int k = 0; k < 4; k++) acc[i][j][k] = 0.f;

    // ldmatrix fragment row addressing (chunk computed per ks)
    const int mat = ln >> 3;       // 0..3
    const int mr  = ln & 7;
    const int aHi = mat >> 1;      // A chunk offset within ks pair
    const int bHi = mat & 1;       // B chunk offset within ks pair
    uint32_t aRowOff[4]; int aRx[4];
#pragma unroll
    for (int mt = 0; mt < 4; mt++) {
        int row = warpM + mt * 16 + ((mat & 1) << 3) + mr;
        aRowOff[mt] = (uint32_t)(row * 128);
        aRx[mt] = row & 7;
    }
    uint32_t bRowOff[4]; int bRx[4];
#pragma unroll
    for (int np = 0; np < 4; np++) {
        int row = warpN + np * 16 + ((mat >> 1) << 3) + mr;
        bRowOff[np] = (uint32_t)(row * 128);
        bRx[np] = row & 7;
    }

    const int KT = K >> 6;

    auto load_stage = [&](int kt, int s) {
        const uint32_t aS = sbase + (uint32_t)s * STAGE;
        const uint32_t bS = aS + ABYTES;
        const __half* Ag = A  + (size_t)bm * K + (size_t)kt * 64;
        const __half* Bg = Bt + (size_t)bn * K + (size_t)kt * 64;
#pragma unroll
        for (int i = 0; i < 8; i++) {
            int l = tid + i * 128;
            int row = l >> 3, kc = l & 7;
            uint32_t soff = (uint32_t)(row * 128 + ((kc ^ (row & 7)) * 16));
            cp_async16(aS + soff, Ag + (size_t)row * K + kc * 8);
            cp_async16(bS + soff, Bg + (size_t)row * K + kc * 8);
        }
        cp_commit();
    };

    load_stage(0, 0);
    load_stage(1, 1);

    for (int kt = 0; kt < KT; kt++) {
        cp_wait<1>();
        __syncthreads();
        if (kt + 2 < KT) load_stage(kt + 2, (kt + 2) % DEPTH);
        else cp_commit();                      // keep group counting uniform

        const uint32_t aB = sbase + (uint32_t)(kt % DEPTH) * STAGE;
        const uint32_t bB = aB + ABYTES;
#pragma unroll
        for (int ks = 0; ks < 4; ks++) {
            uint32_t af[4][4];
#pragma unroll
            for (int mt = 0; mt < 4; mt++)
                ldsm4(af[mt], aB + aRowOff[mt] + (uint32_t)((((2 * ks + aHi) ^ aRx[mt])) * 16));
            uint32_t bf[8][2];
#pragma unroll
            for (int np = 0; np < 4; np++) {
                uint32_t t[4];
                ldsm4(t, bB + bRowOff[np] + (uint32_t)((((2 * ks + bHi) ^ bRx[np])) * 16));
                bf[2 * np][0] = t[0]; bf[2 * np][1] = t[1];
                bf[2 * np + 1][0] = t[2]; bf[2 * np + 1][1] = t[3];
            }
#pragma unroll
            for (int mt = 0; mt < 4; mt++)
#pragma unroll
                for (int nt = 0; nt < 8; nt++)
                    mma16816(acc[mt][nt], af[mt], bf[nt]);
        }
    }

    // epilogue
#pragma unroll
    for (int mt = 0; mt < 4; mt++) {
#pragma unroll
        for (int nt = 0; nt < 8; nt++) {
            int m0 = bm + warpM + mt * 16 + (ln >> 2);
            int n0 = bn + warpN + nt * 8 + (ln & 3) * 2;
            float* a = acc[mt][nt];
            if constexpr (HAS_BIAS) {
                float b0 = bias[n0], b1 = bias[n0 + 1];
                float2 v0 = make_float2(a[0] + b0, a[1] + b1);
                float2 v1 = make_float2(a[2] + b0, a[3] + b1);
                *(float2*)((float*)C + (size_t)m0 * N + n0)       = v0;
                *(float2*)((float*)C + (size_t)(m0 + 8) * N + n0) = v1;
            } else {
                __half2 v0 = __floats2half2_rn(a[0], a[1]);
                __half2 v1 = __floats2half2_rn(a[2], a[3]);
                *(__half2*)((__half*)C + (size_t)m0 * N + n0)       = v0;
                *(__half2*)((__half*)C + (size_t)(m0 + 8) * N + n0) = v1;
            }
        }
    }
}

// ---------------------------------------------------------------------------
extern "C" void kernel_launch(void* const* d_in, const int* in_sizes, int n_in,
                              void* d_out, int out_size)
{
    const float* x    = (const float*)d_in[0];
    const float* w_in = (const float*)d_in[1];
    const float* w_out= (const float*)d_in[2];
    const float* bias = (const float*)d_in[3];
    const float* s_in = (const float*)d_in[4];
    const float* s_out= (const float*)d_in[5];
    float* out = (float*)d_out;

    __half *x16, *h, *win, *wout;
    cudaGetSymbolAddress((void**)&x16,  g_x16);
    cudaGetSymbolAddress((void**)&h,    g_h);
    cudaGetSymbolAddress((void**)&win,  g_win);
    cudaGetSymbolAddress((void**)&wout, g_wout);

    constexpr int SMEM = 3 * (2 * 128 * 128) + 1024;   // 3 stages + align pad

    cudaFuncSetAttribute(gemm_tc<__half, false>,
                         cudaFuncAttributeMaxDynamicSharedMemorySize, SMEM);
    cudaFuncSetAttribute(gemm_tc<float, true>,
                         cudaFuncAttributeMaxDynamicSharedMemorySize, SMEM);

    // 1) x fp32 -> fp16
    convert_x_kernel<<<(MM * (size_t)DD) / (256 * 8), 256>>>(x);
    // 2) soft-threshold weights into B^T fp16 layouts
    prep_win_kernel<<<(DD * (RR / 4)) / 256, 256>>>(w_in, s_in);
    prep_wout_kernel<<<((DD / 4) * RR) / 256, 256>>>(w_out, s_out);

    // 3) stage 1: h[M][R] = x16 @ win^T   grid (4, 64) = 256 CTAs
    {
        dim3 grid(RR / 128, MM / 128);
        gemm_tc<__half, false><<<grid, 128, SMEM>>>(x16, win, h, nullptr, DD, RR);
    }
    // 4) stage 2: out[M][D] = h @ wout^T + bias   grid (16, 64) = 1024 CTAs
    {
        dim3 grid(DD / 128, MM / 128);
        gemm_tc<float, true><<<grid, 128, SMEM>>>(h, wout, out, bias, RR, DD);
    }
}

// round 5
// speedup vs baseline: 1.0826x; 1.0002x over previous
#include <cuda_runtime.h>
#include <cuda_fp16.h>
#include <cstdint>

// Problem-fixed dims: B=4, S=2048 -> M=8192, D=2048, R=512.
#define MM 8192
#define DD 2048
#define RR 512

// Scratch (device globals; no allocation allowed in kernel_launch).
__device__ __half g_x16[MM * (size_t)DD];   // x cast to fp16, [M][D]
__device__ __half g_h[MM * (size_t)RR];     // stage-1 output fp16, [M][R]
__device__ __half g_win[(size_t)RR * DD];   // B^T for stage 1: [N=R][K=D]
__device__ __half g_wout[(size_t)DD * RR];  // B^T for stage 2: [N=D][K=R]

// ---------------------------------------------------------------------------
// helpers
// ---------------------------------------------------------------------------
__device__ __forceinline__ uint32_t smem_u32(const void* p) {
    return (uint32_t)__cvta_generic_to_shared(p);
}
__device__ __forceinline__ void cp_async16(uint32_t saddr, const void* gaddr) {
    asm volatile("cp.async.cg.shared.global [%0], [%1], 16;\n"
                 :: "r"(saddr), "l"(gaddr));
}
__device__ __forceinline__ void cp_commit() {
    asm volatile("cp.async.commit_group;\n");
}
template<int N>
__device__ __forceinline__ void cp_wait() {
    asm volatile("cp.async.wait_group %0;\n" :: "n"(N));
}
__device__ __forceinline__ void ldsm4(uint32_t* r, uint32_t addr) {
    asm volatile("ldmatrix.sync.aligned.m8n8.x4.shared.b16 {%0,%1,%2,%3}, [%4];\n"
                 : "=r"(r[0]), "=r"(r[1]), "=r"(r[2]), "=r"(r[3])
                 : "r"(addr));
}
__device__ __forceinline__ void mma16816(float* c, const uint32_t* a, const uint32_t* b) {
    asm volatile(
        "mma.sync.aligned.m16n8k16.row.col.f32.f16.f16.f32 "
        "{%0,%1,%2,%3}, {%4,%5,%6,%7}, {%8,%9}, {%0,%1,%2,%3};\n"
        : "+f"(c[0]), "+f"(c[1]), "+f"(c[2]), "+f"(c[3])
        : "r"(a[0]), "r"(a[1]), "r"(a[2]), "r"(a[3]), "r"(b[0]), "r"(b[1]));
}

// ---------------------------------------------------------------------------
// preprocessing kernels
// ---------------------------------------------------------------------------
__global__ void convert_x_kernel(const float* __restrict__ x) {
    size_t i = ((size_t)blockIdx.x * blockDim.x + threadIdx.x) * 8;
    float4 a = *(const float4*)(x + i);
    float4 b = *(const float4*)(x + i + 4);
    __half2 h0 = __floats2half2_rn(a.x, a.y);
    __half2 h1 = __floats2half2_rn(a.z, a.w);
    __half2 h2 = __floats2half2_rn(b.x, b.y);
    __half2 h3 = __floats2half2_rn(b.z, b.w);
    uint4 v;
    v.x = *(uint32_t*)&h0; v.y = *(uint32_t*)&h1;
    v.z = *(uint32_t*)&h2; v.w = *(uint32_t*)&h3;
    *(uint4*)(g_x16 + i) = v;
}

__device__ __forceinline__ float second_smallest4(float a0, float a1, float a2, float a3) {
    float lo01 = fminf(a0, a1), hi01 = fmaxf(a0, a1);
    float lo23 = fminf(a2, a3), hi23 = fmaxf(a2, a3);
    return fminf(fmaxf(lo01, lo23), fminf(hi01, hi23));
}
__device__ __forceinline__ float shrink1(float w, float t, float s) {
    float a = fabsf(w) - t;
    a = a > 0.f ? a : 0.f;
    return copysignf(a, w) * s;
}

__global__ void prep_win_kernel(const float* __restrict__ w, const float* __restrict__ scale_p) {
    int idx = blockIdx.x * blockDim.x + threadIdx.x;
    int d  = idx >> 7;
    int rg = idx & 127;
    float4 wv = *(const float4*)(w + (size_t)d * RR + rg * 4);
    float s = *scale_p;
    float t = second_smallest4(fabsf(wv.x), fabsf(wv.y), fabsf(wv.z), fabsf(wv.w));
    int r0 = rg * 4;
    g_win[(size_t)(r0 + 0) * DD + d] = __float2half_rn(shrink1(wv.x, t, s));
    g_win[(size_t)(r0 + 1) * DD + d] = __float2half_rn(shrink1(wv.y, t, s));
    g_win[(size_t)(r0 + 2) * DD + d] = __float2half_rn(shrink1(wv.z, t, s));
    g_win[(size_t)(r0 + 3) * DD + d] = __float2half_rn(shrink1(wv.w, t, s));
}

__global__ void prep_wout_kernel(const float* __restrict__ w, const float* __restrict__ scale_p) {
    int idx = blockIdx.x * blockDim.x + threadIdx.x;
    int dg = idx >> 9;
    int r  = idx & 511;
    int d0 = dg * 4;
    float w0 = w[(size_t)(d0 + 0) * RR + r];
    float w1 = w[(size_t)(d0 + 1) * RR + r];
    float w2 = w[(size_t)(d0 + 2) * RR + r];
    float w3 = w[(size_t)(d0 + 3) * RR + r];
    float s = *scale_p;
    float t = second_smallest4(fabsf(w0), fabsf(w1), fabsf(w2), fabsf(w3));
    g_wout[(size_t)(d0 + 0) * RR + r] = __float2half_rn(shrink1(w0, t, s));
    g_wout[(size_t)(d0 + 1) * RR + r] = __float2half_rn(shrink1(w1, t, s));
    g_wout[(size_t)(d0 + 2) * RR + r] = __float2half_rn(shrink1(w2, t, s));
    g_wout[(size_t)(d0 + 3) * RR + r] = __float2half_rn(shrink1(w3, t, s));
}

// ---------------------------------------------------------------------------
// HMMA GEMM: C[M][N] = A[M][K] * Bt[N][K], fp16 in, fp32 acc.
// BM=128, BN=128, BK=64. 128 threads, 4 warps in 2x2, warp tile 64x64.
// DEPTH=3 cp.async ring, one __syncthreads per K-iter.
// Fragment double-buffering: ldmatrix for ks+1 issued before the 32 MMAs
// of ks, hiding LDS latency inside the MMA stream.
// ---------------------------------------------------------------------------
template<typename OutT, bool HAS_BIAS>
__global__ __launch_bounds__(128, 2) void gemm_tc(
    const __half* __restrict__ A, const __half* __restrict__ Bt,
    OutT* __restrict__ C, const float* __restrict__ bias, int K, int N)
{
    constexpr int ABYTES = 128 * 128;      // 128 rows x 64 halves
    constexpr int STAGE  = 2 * ABYTES;     // A + B
    constexpr int DEPTH  = 3;

    extern __shared__ __align__(1024) uint8_t dsmem[];
    const uint32_t sbase = (smem_u32(dsmem) + 1023u) & ~1023u;

    const int tid = threadIdx.x;
    const int wid = tid >> 5, ln = tid & 31;
    const int bm = blockIdx.y * 128, bn = blockIdx.x * 128;
    const int warpM = (wid >> 1) * 64;
    const int warpN = (wid & 1) * 64;

    float acc[4][8][4];
#pragma unroll
    for (int i = 0; i < 4; i++)
#pragma unroll
        for (int j = 0; j < 8; j++)
#pragma unroll
            for (int k = 0; k < 4; k++) acc[i][j][k] = 0.f;

    // ldmatrix fragment row addressing (chunk computed per ks)
    const int mat = ln >> 3;       // 0..3
    const int mr  = ln & 7;
    const int aHi = mat >> 1;      // A chunk offset within ks pair
    const int bHi = mat & 1;       // B chunk offset within ks pair
    uint32_t aRowOff[4]; int aRx[4];
#pragma unroll
    for (int mt = 0; mt < 4; mt++) {
        int row = warpM + mt * 16 + ((mat & 1) << 3) + mr;
        aRowOff[mt] = (uint32_t)(row * 128);
        aRx[mt] = row & 7;
    }
    uint32_t bRowOff[4]; int bRx[4];
#pragma unroll
    for (int np = 0; np < 4; np++) {
        int row = warpN + np * 16 + ((mat >> 1) << 3) + mr;
        bRowOff[np] = (uint32_t)(row * 128);
        bRx[np] = row & 7;
    }

    const int KT = K >> 6;

    auto load_stage = [&](int kt, int s) {
        const uint32_t aS = sbase + (uint32_t)s * STAGE;
        const uint32_t bS = aS + ABYTES;
        const __half* Ag = A  + (size_t)bm * K + (size_t)kt * 64;
        const __half* Bg = Bt + (size_t)bn * K + (size_t)kt * 64;
#pragma unroll
        for (int i = 0; i < 8; i++) {
            int l = tid + i * 128;
            int row = l >> 3, kc = l & 7;
            uint32_t soff = (uint32_t)(row * 128 + ((kc ^ (row & 7)) * 16));
            cp_async16(aS + soff, Ag + (size_t)row * K + kc * 8);
            cp_async16(bS + soff, Bg + (size_t)row * K + kc * 8);
        }
        cp_commit();
    };

    // fragment loader for one ks step
    auto load_frags = [&](uint32_t aB, uint32_t bB, int ks,
                          uint32_t af[4][4], uint32_t bf[8][2]) {
#pragma unroll
        for (int mt = 0; mt < 4; mt++)
            ldsm4(af[mt], aB + aRowOff[mt] + (uint32_t)((((2 * ks + aHi) ^ aRx[mt])) * 16));
#pragma unroll
        for (int np = 0; np < 4; np++) {
            uint32_t t[4];
            ldsm4(t, bB + bRowOff[np] + (uint32_t)((((2 * ks + bHi) ^ bRx[np])) * 16));
            bf[2 * np][0] = t[0]; bf[2 * np][1] = t[1];
            bf[2 * np + 1][0] = t[2]; bf[2 * np + 1][1] = t[3];
        }
    };

    load_stage(0, 0);
    load_stage(1, 1);

    uint32_t afb[2][4][4], bfb[2][8][2];

    for (int kt = 0; kt < KT; kt++) {
        cp_wait<1>();
        __syncthreads();
        if (kt + 2 < KT) load_stage(kt + 2, (kt + 2) % DEPTH);
        else cp_commit();                      // keep group counting uniform

        const uint32_t aB = sbase + (uint32_t)(kt % DEPTH) * STAGE;
        const uint32_t bB = aB + ABYTES;

        load_frags(aB, bB, 0, afb[0], bfb[0]);
#pragma unroll
        for (int ks = 0; ks < 4; ks++) {
            const int cur = ks & 1;
            if (ks < 3)
                load_frags(aB, bB, ks + 1, afb[cur ^ 1], bfb[cur ^ 1]);
#pragma unroll
            for (int mt = 0; mt < 4; mt++)
#pragma unroll
                for (int nt = 0; nt < 8; nt++)
                    mma16816(acc[mt][nt], afb[cur][mt], bfb[cur][nt]);
        }
    }

    // epilogue
#pragma unroll
    for (int mt = 0; mt < 4; mt++) {
#pragma unroll
        for (int nt = 0; nt < 8; nt++) {
            int m0 = bm + warpM + mt * 16 + (ln >> 2);
            int n0 = bn + warpN + nt * 8 + (ln & 3) * 2;
            float* a = acc[mt][nt];
            if constexpr (HAS_BIAS) {
                float b0 = bias[n0], b1 = bias[n0 + 1];
                float2 v0 = make_float2(a[0] + b0, a[1] + b1);
                float2 v1 = make_float2(a[2] + b0, a[3] + b1);
                *(float2*)((float*)C + (size_t)m0 * N + n0)       = v0;
                *(float2*)((float*)C + (size_t)(m0 + 8) * N + n0) = v1;
            } else {
                __half2 v0 = __floats2half2_rn(a[0], a[1]);
                __half2 v1 = __floats2half2_rn(a[2], a[3]);
                *(__half2*)((__half*)C + (size_t)m0 * N + n0)       = v0;
                *(__half2*)((__half*)C + (size_t)(m0 + 8) * N + n0) = v1;
            }
        }
    }
}

// ---------------------------------------------------------------------------
extern "C" void kernel_launch(void* const* d_in, const int* in_sizes, int n_in,
                              void* d_out, int out_size)
{
    const float* x    = (const float*)d_in[0];
    const float* w_in = (const float*)d_in[1];
    const float* w_out= (const float*)d_in[2];
    const float* bias = (const float*)d_in[3];
    const float* s_in = (const float*)d_in[4];
    const float* s_out= (const float*)d_in[5];
    float* out = (float*)d_out;

    __half *x16, *h, *win, *wout;
    cudaGetSymbolAddress((void**)&x16,  g_x16);
    cudaGetSymbolAddress((void**)&h,    g_h);
    cudaGetSymbolAddress((void**)&win,  g_win);
    cudaGetSymbolAddress((void**)&wout, g_wout);

    constexpr int SMEM = 3 * (2 * 128 * 128) + 1024;   // 3 stages + align pad

    cudaFuncSetAttribute(gemm_tc<__half, false>,
                         cudaFuncAttributeMaxDynamicSharedMemorySize, SMEM);
    cudaFuncSetAttribute(gemm_tc<float, true>,
                         cudaFuncAttributeMaxDynamicSharedMemorySize, SMEM);

    // 1) x fp32 -> fp16
    convert_x_kernel<<<(MM * (size_t)DD) / (256 * 8), 256>>>(x);
    // 2) soft-threshold weights into B^T fp16 layouts
    prep_win_kernel<<<(DD * (RR / 4)) / 256, 256>>>(w_in, s_in);
    prep_wout_kernel<<<((DD / 4) * RR) / 256, 256>>>(w_out, s_out);

    // 3) stage 1: h[M][R] = x16 @ win^T   grid (4, 64) = 256 CTAs
    {
        dim3 grid(RR / 128, MM / 128);
        gemm_tc<__half, false><<<grid, 128, SMEM>>>(x16, win, h, nullptr, DD, RR);
    }
    // 4) stage 2: out[M][D] = h @ wout^T + bias   grid (16, 64) = 1024 CTAs
    {
        dim3 grid(DD / 128, MM / 128);
        gemm_tc<float, true><<<grid, 128, SMEM>>>(h, wout, out, bias, RR, DD);
    }
}